// round 4
// baseline (speedup 1.0000x reference)
#include <cuda_runtime.h>
#include <cstdint>
#include <cstddef>

// ---------------------------------------------------------------------------
// Scratch: x_proj buffer [B*T, H] = [262144, 256] fp32 = 256 MiB
// ---------------------------------------------------------------------------
__device__ float g_xproj[64u * 4096u * 256u];

// ---------------------------------------------------------------------------
// Accurate tanh independent of --use_fast_math (EX2-based, ~1e-6 rel err)
// ---------------------------------------------------------------------------
__device__ __forceinline__ float my_tanh(float x) {
    float ax = fabsf(x);
    float e = exp2f(ax * 2.88539008177793f);   // 2*log2(e)
    float t = 1.0f - 2.0f / (e + 1.0f);
    if (ax > 15.0f) t = 1.0f;
    return copysignf(t, x);
}

// ---------------------------------------------------------------------------
// Packed f32x2 helpers
// ---------------------------------------------------------------------------
__device__ __forceinline__ uint64_t ffma2(uint64_t a, uint64_t b, uint64_t c) {
    uint64_t d;
    asm("fma.rn.f32x2 %0, %1, %2, %3;" : "=l"(d) : "l"(a), "l"(b), "l"(c));
    return d;
}
__device__ __forceinline__ float f2sum(uint64_t v) {
    float lo, hi;
    asm("mov.b64 {%0, %1}, %2;" : "=f"(lo), "=f"(hi) : "l"(v));
    return lo + hi;
}
__device__ __forceinline__ uint64_t pack2(float lo, float hi) {
    uint64_t d;
    asm("mov.b64 %0, {%1, %2};" : "=l"(d) : "f"(lo), "f"(hi));
    return d;
}
__device__ __forceinline__ void unpack2(uint64_t v, float& lo, float& hi) {
    asm("mov.b64 {%0, %1}, %2;" : "=f"(lo), "=f"(hi) : "l"(v));
}

__device__ __forceinline__ uint32_t smem_u32(const void* p) {
    uint32_t a;
    asm("{ .reg .u64 t; cvta.to.shared.u64 t, %1; cvt.u32.u64 %0, t; }"
        : "=r"(a) : "l"(p));
    return a;
}
__device__ __forceinline__ uint32_t mapa_rank(uint32_t laddr, uint32_t rank) {
    uint32_t raddr;
    asm("mapa.shared::cluster.u32 %0, %1, %2;" : "=r"(raddr) : "r"(laddr), "r"(rank));
    return raddr;
}
// Async store of 4 bytes completing tx on the given (cluster-addr) mbarrier.
__device__ __forceinline__ void st_async_f32(uint32_t raddr, float v, uint32_t rmbar) {
    asm volatile(
        "st.async.shared::cluster.mbarrier::complete_tx::bytes.b32 [%0], %1, [%2];"
        :: "r"(raddr), "r"(__float_as_uint(v)), "r"(rmbar) : "memory");
}
__device__ __forceinline__ void mbar_init(uint32_t addr, uint32_t cnt) {
    asm volatile("mbarrier.init.shared.b64 [%0], %1;" :: "r"(addr), "r"(cnt) : "memory");
}
__device__ __forceinline__ void mbar_arrive_expect_tx(uint32_t addr, uint32_t tx) {
    asm volatile("mbarrier.arrive.expect_tx.shared.b64 _, [%0], %1;"
                 :: "r"(addr), "r"(tx) : "memory");
}
__device__ __forceinline__ void mbar_wait_parity(uint32_t addr, uint32_t parity) {
    uint32_t done;
    asm volatile(
        "{\n\t.reg .pred p;\n\t"
        "mbarrier.try_wait.parity.acquire.cta.shared::cta.b64 p, [%1], %2;\n\t"
        "selp.b32 %0, 1, 0, p;\n\t}"
        : "=r"(done) : "r"(addr), "r"(parity) : "memory");
    if (!done) {
        asm volatile(
            "{\n\t.reg .pred P1;\n\t"
            "WL_%=:\n\t"
            "mbarrier.try_wait.parity.acquire.cta.shared::cta.b64 P1, [%0], %1, 0x989680;\n\t"
            "@P1 bra.uni WD_%=;\n\t"
            "bra.uni WL_%=;\n\t"
            "WD_%=:\n\t}"
            :: "r"(addr), "r"(parity) : "memory");
    }
}

#define CLUSTER_SYNC_() do { \
    asm volatile("barrier.cluster.arrive.aligned;" ::: "memory"); \
    asm volatile("barrier.cluster.wait.aligned;" ::: "memory"); } while (0)

// ---------------------------------------------------------------------------
// Kernel 1: x_proj = x @ W_in^T + b_in
//   128x128 tile, BK=16, 256 threads, 8x8 micro-tile with packed f32x2 FMA.
// ---------------------------------------------------------------------------
#define XP_BM 128
#define XP_BN 128
#define XP_BK 16

__global__ __launch_bounds__(256) void xproj_kernel(
    const float* __restrict__ x, const float* __restrict__ Win,
    const float* __restrict__ bin, float* __restrict__ out,
    int M, int K, int N)
{
    __shared__ float As[XP_BK][XP_BM];
    __shared__ float Bs[XP_BK][XP_BN];

    const int tid = threadIdx.x;
    const int tx = tid & 15;          // N direction (8 cols each)
    const int ty = tid >> 4;          // M direction (8 rows each)
    const int n0 = blockIdx.x * XP_BN;
    const int m0 = blockIdx.y * XP_BM;

    const int lr = tid >> 1;          // 0..127 row
    const int lc = (tid & 1) * 8;     // 0 or 8 k-offset

    uint64_t cc[8][4];                // 8 M-rows x 4 packed-N-pairs
    #pragma unroll
    for (int i = 0; i < 8; i++)
        #pragma unroll
        for (int jj = 0; jj < 4; jj++) cc[i][jj] = 0ull;

    for (int k0 = 0; k0 < K; k0 += XP_BK) {
        float4 xa0 = *(const float4*)(x   + (size_t)(m0 + lr) * K + k0 + lc);
        float4 xa1 = *(const float4*)(x   + (size_t)(m0 + lr) * K + k0 + lc + 4);
        float4 wb0 = *(const float4*)(Win + (size_t)(n0 + lr) * K + k0 + lc);
        float4 wb1 = *(const float4*)(Win + (size_t)(n0 + lr) * K + k0 + lc + 4);
        As[lc + 0][lr] = xa0.x; As[lc + 1][lr] = xa0.y;
        As[lc + 2][lr] = xa0.z; As[lc + 3][lr] = xa0.w;
        As[lc + 4][lr] = xa1.x; As[lc + 5][lr] = xa1.y;
        As[lc + 6][lr] = xa1.z; As[lc + 7][lr] = xa1.w;
        Bs[lc + 0][lr] = wb0.x; Bs[lc + 1][lr] = wb0.y;
        Bs[lc + 2][lr] = wb0.z; Bs[lc + 3][lr] = wb0.w;
        Bs[lc + 4][lr] = wb1.x; Bs[lc + 5][lr] = wb1.y;
        Bs[lc + 6][lr] = wb1.z; Bs[lc + 7][lr] = wb1.w;
        __syncthreads();

        #pragma unroll
        for (int kk = 0; kk < XP_BK; kk++) {
            float4 a0 = *(const float4*)(&As[kk][ty * 8]);
            float4 a1 = *(const float4*)(&As[kk][ty * 8 + 4]);
            ulonglong2 b0 = *(const ulonglong2*)(&Bs[kk][tx * 8]);
            ulonglong2 b1 = *(const ulonglong2*)(&Bs[kk][tx * 8 + 4]);
            float av[8] = {a0.x, a0.y, a0.z, a0.w, a1.x, a1.y, a1.z, a1.w};
            uint64_t bp[4] = {b0.x, b0.y, b1.x, b1.y};
            #pragma unroll
            for (int mi = 0; mi < 8; mi++) {
                uint64_t ap = pack2(av[mi], av[mi]);
                #pragma unroll
                for (int ni = 0; ni < 4; ni++)
                    cc[mi][ni] = ffma2(ap, bp[ni], cc[mi][ni]);
            }
        }
        __syncthreads();
    }

    float bb[8];
    #pragma unroll
    for (int ni = 0; ni < 8; ni++) bb[ni] = __ldg(&bin[n0 + tx * 8 + ni]);

    #pragma unroll
    for (int mi = 0; mi < 8; mi++) {
        int row = m0 + ty * 8 + mi;
        float c[8];
        #pragma unroll
        for (int ni = 0; ni < 4; ni++) unpack2(cc[mi][ni], c[2 * ni], c[2 * ni + 1]);
        float4 o0 = make_float4(c[0] + bb[0], c[1] + bb[1], c[2] + bb[2], c[3] + bb[3]);
        float4 o1 = make_float4(c[4] + bb[4], c[5] + bb[5], c[6] + bb[6], c[7] + bb[7]);
        *(float4*)(out + (size_t)row * N + n0 + tx * 8)     = o0;
        *(float4*)(out + (size_t)row * N + n0 + tx * 8 + 4) = o1;
    }
}

// ---------------------------------------------------------------------------
// Kernel 2: LTC scan, 2-CTA cluster per batch, hybrid J+K split.
//   CTA rank r owns outputs j = r*128 + p (p = tid>>1); lane kh = tid&1 does
//   K-columns [kh*128, kh*128+128) (64 packed f32x2 regs).
//   After shfl-pair-reduce + tanh + h-update:
//     even lane st.asyncs h_j -> OWN  hbuf[slot][j] (own   mbar[slot])
//     odd  lane st.asyncs h_j -> PEER hbuf[slot][j] (peer  mbar[slot])
//   Each CTA's mbar[slot] expects 256 stores * 4B = 1024B per phase
//   (128 local + 128 remote). ONE mbar wait per iteration; no __syncthreads,
//   no cluster barrier in the loop.
//   Arm protocol (race-free): slot s's next phase is armed immediately after
//   the wait that closes its previous phase — strictly before either CTA's
//   stores for that phase (peer's are gated by our previous-slot st.async).
// ---------------------------------------------------------------------------
#define LTC_H 256

__global__ __launch_bounds__(256, 1) __cluster_dims__(2, 1, 1)
void ltc_scan_kernel(
    const float* __restrict__ xproj,
    const float* __restrict__ Wrec,
    const float* __restrict__ brec,
    const float* __restrict__ tau,
    const int*   __restrict__ nl_p,
    float* __restrict__ out, int T)
{
    __shared__ __align__(16) float hbuf[2][LTC_H];
    __shared__ __align__(16) unsigned long long mbar[2];

    const int b = blockIdx.x >> 1;
    uint32_t rank;
    asm("mov.u32 %0, %%cluster_ctarank;" : "=r"(rank));
    const uint32_t peer = rank ^ 1u;

    const int t_ = threadIdx.x;
    const int p  = t_ >> 1;                 // pair index 0..127
    const int kh = t_ & 1;                  // K-half
    const int j  = (int)rank * 128 + p;     // owned output

    // --- W_rec[j][kh*128 .. +127] -> 64 packed f32x2 registers ------------
    uint64_t wd[64];
    {
        const ulonglong2* wrow =
            (const ulonglong2*)(Wrec + (size_t)j * LTC_H + (kh << 7));
        #pragma unroll
        for (int i = 0; i < 32; i++) {
            ulonglong2 v = wrow[i];
            wd[2 * i]     = v.x;
            wd[2 * i + 1] = v.y;
        }
    }

    const float brec_j = brec[j];
    const float scale_j = 0.1f / fminf(fmaxf(tau[j], 0.1f), 5.0f);

    int NL = 2;
    if (nl_p) {
        int v = *nl_p;
        if (v >= 1 && v <= 64) NL = v;
    }

    // --- init: mbars, zero h, arm both slots' phase 0 ---------------------
    const uint32_t mb[2] = { smem_u32(&mbar[0]), smem_u32(&mbar[1]) };
    if (t_ == 0) {
        mbar_init(mb[0], 1);
        mbar_init(mb[1], 1);
    }
    hbuf[0][t_] = 0.0f;
    hbuf[1][t_] = 0.0f;
    __syncthreads();
    if (t_ == 0) {
        mbar_arrive_expect_tx(mb[0], LTC_H * 4u);
        mbar_arrive_expect_tx(mb[1], LTC_H * 4u);
    }
    asm volatile("fence.proxy.async.shared::cta;" ::: "memory");
    __syncthreads();
    CLUSTER_SYNC_();   // peer mbars armed + h zeros visible before any st.async

    // store targets: even lane -> own CTA, odd lane -> peer CTA
    const uint32_t dst_rank = kh ? peer : rank;
    const uint32_t st_addr[2] = {
        mapa_rank(smem_u32(&hbuf[0][j]), dst_rank),
        mapa_rank(smem_u32(&hbuf[1][j]), dst_rank)
    };
    const uint32_t st_mbar[2] = {
        mapa_rank(mb[0], dst_rank),
        mapa_rank(mb[1], dst_rank)
    };

    const float* xrow = xproj + ((size_t)b * T) * LTC_H + j;
    float xt = __ldg(xrow);            // prefetch t = 0
    float hj = 0.0f;
    unsigned it = 0;
    uint32_t ph0 = 0, ph1 = 0;

    for (int t = 0; t < T; t++) {
        const float base = xt + brec_j;
        if (t + 1 < T) xt = __ldg(xrow + (size_t)(t + 1) * LTC_H);

        for (int l = 0; l < NL; l++) {
            const int rs = (it + 1) & 1;   // slot holding h from iteration it-1

            if (it != 0) {
                if (rs == 0) {
                    mbar_wait_parity(mb[0], ph0); ph0 ^= 1;
                } else {
                    mbar_wait_parity(mb[1], ph1); ph1 ^= 1;
                }
                // re-arm this slot for its NEXT phase (written at it+1)
                if (t_ == 0) mbar_arrive_expect_tx(mb[rs], LTC_H * 4u);
            }

            // ---- partial dot product over my K-half ----
            const ulonglong2* hp = (const ulonglong2*)(hbuf[rs] + (kh << 7));
            uint64_t a0 = 0ull, a1 = 0ull, a2 = 0ull, a3 = 0ull;
            #pragma unroll
            for (int i = 0; i < 32; i += 2) {
                ulonglong2 h0 = hp[i];
                ulonglong2 h1 = hp[i + 1];
                a0 = ffma2(wd[2 * i],     h0.x, a0);
                a1 = ffma2(wd[2 * i + 1], h0.y, a1);
                a2 = ffma2(wd[2 * i + 2], h1.x, a2);
                a3 = ffma2(wd[2 * i + 3], h1.y, a3);
            }
            float part = (f2sum(a0) + f2sum(a1)) + (f2sum(a2) + f2sum(a3));
            // pair reduction (lanes 2m / 2m+1 hold the two K-halves)
            const float sum = part + __shfl_xor_sync(0xffffffffu, part, 1);

            const float act = my_tanh(base + sum);
            hj = fmaf(scale_j, act - hj, hj);

            // ---- publish h_j: even->own hbuf, odd->peer hbuf -------------
            const int ws = it & 1;
            st_async_f32(st_addr[ws], hj, st_mbar[ws]);
            it++;
        }
    }

    if (kh == 0) out[(size_t)b * LTC_H + j] = hj;

    CLUSTER_SYNC_();   // don't exit while peer st.async may target our smem
}

// ---------------------------------------------------------------------------
// Launcher — inputs: x, W_in, b_in, W_rec, b_rec, tau, num_layers
// ---------------------------------------------------------------------------
extern "C" void kernel_launch(void* const* d_in, const int* in_sizes, int n_in,
                              void* d_out, int out_size)
{
    const float* x    = (const float*)d_in[0];
    const float* Win  = (const float*)d_in[1];
    const float* bin  = (const float*)d_in[2];
    const float* Wrec = (const float*)d_in[3];
    const float* brec = (const float*)d_in[4];
    const float* tau  = (const float*)d_in[5];
    const int*   nl   = (n_in > 6) ? (const int*)d_in[6] : nullptr;

    const int H = in_sizes[2];              // 256
    const int I = in_sizes[1] / H;          // 128
    const int B = out_size / H;             // 64
    const int T = in_sizes[0] / (B * I);    // 4096
    const int M = B * T;

    float* xproj = nullptr;
    cudaGetSymbolAddress((void**)&xproj, g_xproj);

    dim3 grid1(H / XP_BN, M / XP_BM);
    xproj_kernel<<<grid1, 256>>>(x, Win, bin, xproj, M, I, H);

    ltc_scan_kernel<<<2 * B, LTC_H>>>(xproj, Wrec, brec, tau, nl,
                                      (float*)d_out, T);
}

// round 5
// speedup vs baseline: 1.4318x; 1.4318x over previous
#include <cuda_runtime.h>
#include <cstdint>
#include <cstddef>

// ---------------------------------------------------------------------------
// Scratch: x_proj buffer [B*T, H] = [262144, 256] fp32 = 256 MiB
// ---------------------------------------------------------------------------
__device__ float g_xproj[64u * 4096u * 256u];

// ---------------------------------------------------------------------------
// Branch-free tanh: 1 - 2/(e^{2x}+1), explicit MUFU path.
//   x -> +inf: ex2 -> inf, rcp -> 0, t -> 1.  x -> -inf: ex2 -> 0, t -> -1.
// ---------------------------------------------------------------------------
__device__ __forceinline__ float my_tanh(float x) {
    float e;
    asm("ex2.approx.f32 %0, %1;" : "=f"(e) : "f"(x * 2.8853900817779268f));
    float r;
    asm("rcp.approx.f32 %0, %1;" : "=f"(r) : "f"(e + 1.0f));
    return fmaf(-2.0f, r, 1.0f);
}

// ---------------------------------------------------------------------------
// Packed f32x2 helpers
// ---------------------------------------------------------------------------
__device__ __forceinline__ uint64_t ffma2(uint64_t a, uint64_t b, uint64_t c) {
    uint64_t d;
    asm("fma.rn.f32x2 %0, %1, %2, %3;" : "=l"(d) : "l"(a), "l"(b), "l"(c));
    return d;
}
__device__ __forceinline__ float f2sum(uint64_t v) {
    float lo, hi;
    asm("mov.b64 {%0, %1}, %2;" : "=f"(lo), "=f"(hi) : "l"(v));
    return lo + hi;
}
__device__ __forceinline__ uint64_t pack2(float lo, float hi) {
    uint64_t d;
    asm("mov.b64 %0, {%1, %2};" : "=l"(d) : "f"(lo), "f"(hi));
    return d;
}
__device__ __forceinline__ void unpack2(uint64_t v, float& lo, float& hi) {
    asm("mov.b64 {%0, %1}, %2;" : "=f"(lo), "=f"(hi) : "l"(v));
}

__device__ __forceinline__ uint32_t smem_u32(const void* p) {
    uint32_t a;
    asm("{ .reg .u64 t; cvta.to.shared.u64 t, %1; cvt.u32.u64 %0, t; }"
        : "=r"(a) : "l"(p));
    return a;
}
__device__ __forceinline__ uint32_t mapa_rank(uint32_t laddr, uint32_t rank) {
    uint32_t raddr;
    asm("mapa.shared::cluster.u32 %0, %1, %2;" : "=r"(raddr) : "r"(laddr), "r"(rank));
    return raddr;
}
// Async 8-byte store completing tx on the given (cluster-addr) mbarrier.
__device__ __forceinline__ void st_async_b64(uint32_t raddr, uint64_t v, uint32_t rmbar) {
    asm volatile(
        "st.async.shared::cluster.mbarrier::complete_tx::bytes.b64 [%0], %1, [%2];"
        :: "r"(raddr), "l"(v), "r"(rmbar) : "memory");
}
__device__ __forceinline__ void mbar_init(uint32_t addr, uint32_t cnt) {
    asm volatile("mbarrier.init.shared.b64 [%0], %1;" :: "r"(addr), "r"(cnt) : "memory");
}
__device__ __forceinline__ void mbar_arrive_expect_tx(uint32_t addr, uint32_t tx) {
    asm volatile("mbarrier.arrive.expect_tx.shared.b64 _, [%0], %1;"
                 :: "r"(addr), "r"(tx) : "memory");
}
__device__ __forceinline__ void mbar_wait_parity(uint32_t addr, uint32_t parity) {
    uint32_t done;
    asm volatile(
        "{\n\t.reg .pred p;\n\t"
        "mbarrier.try_wait.parity.acquire.cta.shared::cta.b64 p, [%1], %2;\n\t"
        "selp.b32 %0, 1, 0, p;\n\t}"
        : "=r"(done) : "r"(addr), "r"(parity) : "memory");
    if (!done) {
        asm volatile(
            "{\n\t.reg .pred P1;\n\t"
            "WL_%=:\n\t"
            "mbarrier.try_wait.parity.acquire.cta.shared::cta.b64 P1, [%0], %1, 0x989680;\n\t"
            "@P1 bra.uni WD_%=;\n\t"
            "bra.uni WL_%=;\n\t"
            "WD_%=:\n\t}"
            :: "r"(addr), "r"(parity) : "memory");
    }
}

#define CLUSTER_SYNC_() do { \
    asm volatile("barrier.cluster.arrive.aligned;" ::: "memory"); \
    asm volatile("barrier.cluster.wait.aligned;" ::: "memory"); } while (0)

// ---------------------------------------------------------------------------
// Kernel 1: x_proj = x @ W_in^T + b_in  (128x128 tile, packed f32x2 FMA)
// ---------------------------------------------------------------------------
#define XP_BM 128
#define XP_BN 128
#define XP_BK 16

__global__ __launch_bounds__(256) void xproj_kernel(
    const float* __restrict__ x, const float* __restrict__ Win,
    const float* __restrict__ bin, float* __restrict__ out,
    int M, int K, int N)
{
    __shared__ float As[XP_BK][XP_BM];
    __shared__ float Bs[XP_BK][XP_BN];

    const int tid = threadIdx.x;
    const int tx = tid & 15;
    const int ty = tid >> 4;
    const int n0 = blockIdx.x * XP_BN;
    const int m0 = blockIdx.y * XP_BM;

    const int lr = tid >> 1;
    const int lc = (tid & 1) * 8;

    uint64_t cc[8][4];
    #pragma unroll
    for (int i = 0; i < 8; i++)
        #pragma unroll
        for (int jj = 0; jj < 4; jj++) cc[i][jj] = 0ull;

    for (int k0 = 0; k0 < K; k0 += XP_BK) {
        float4 xa0 = *(const float4*)(x   + (size_t)(m0 + lr) * K + k0 + lc);
        float4 xa1 = *(const float4*)(x   + (size_t)(m0 + lr) * K + k0 + lc + 4);
        float4 wb0 = *(const float4*)(Win + (size_t)(n0 + lr) * K + k0 + lc);
        float4 wb1 = *(const float4*)(Win + (size_t)(n0 + lr) * K + k0 + lc + 4);
        As[lc + 0][lr] = xa0.x; As[lc + 1][lr] = xa0.y;
        As[lc + 2][lr] = xa0.z; As[lc + 3][lr] = xa0.w;
        As[lc + 4][lr] = xa1.x; As[lc + 5][lr] = xa1.y;
        As[lc + 6][lr] = xa1.z; As[lc + 7][lr] = xa1.w;
        Bs[lc + 0][lr] = wb0.x; Bs[lc + 1][lr] = wb0.y;
        Bs[lc + 2][lr] = wb0.z; Bs[lc + 3][lr] = wb0.w;
        Bs[lc + 4][lr] = wb1.x; Bs[lc + 5][lr] = wb1.y;
        Bs[lc + 6][lr] = wb1.z; Bs[lc + 7][lr] = wb1.w;
        __syncthreads();

        #pragma unroll
        for (int kk = 0; kk < XP_BK; kk++) {
            float4 a0 = *(const float4*)(&As[kk][ty * 8]);
            float4 a1 = *(const float4*)(&As[kk][ty * 8 + 4]);
            ulonglong2 b0 = *(const ulonglong2*)(&Bs[kk][tx * 8]);
            ulonglong2 b1 = *(const ulonglong2*)(&Bs[kk][tx * 8 + 4]);
            float av[8] = {a0.x, a0.y, a0.z, a0.w, a1.x, a1.y, a1.z, a1.w};
            uint64_t bp[4] = {b0.x, b0.y, b1.x, b1.y};
            #pragma unroll
            for (int mi = 0; mi < 8; mi++) {
                uint64_t ap = pack2(av[mi], av[mi]);
                #pragma unroll
                for (int ni = 0; ni < 4; ni++)
                    cc[mi][ni] = ffma2(ap, bp[ni], cc[mi][ni]);
            }
        }
        __syncthreads();
    }

    float bb[8];
    #pragma unroll
    for (int ni = 0; ni < 8; ni++) bb[ni] = __ldg(&bin[n0 + tx * 8 + ni]);

    #pragma unroll
    for (int mi = 0; mi < 8; mi++) {
        int row = m0 + ty * 8 + mi;
        float c[8];
        #pragma unroll
        for (int ni = 0; ni < 4; ni++) unpack2(cc[mi][ni], c[2 * ni], c[2 * ni + 1]);
        float4 o0 = make_float4(c[0] + bb[0], c[1] + bb[1], c[2] + bb[2], c[3] + bb[3]);
        float4 o1 = make_float4(c[4] + bb[4], c[5] + bb[5], c[6] + bb[6], c[7] + bb[7]);
        *(float4*)(out + (size_t)row * N + n0 + tx * 8)     = o0;
        *(float4*)(out + (size_t)row * N + n0 + tx * 8 + 4) = o1;
    }
}

// ---------------------------------------------------------------------------
// Kernel 2: LTC scan, 2-CTA cluster per batch, K-SPLIT (R3 architecture).
//   Thread t owns output t; computes partial over K-cols [rank*128,+128)
//   (64 packed f32x2 regs). Partials cross to the peer via st.async.b64
//   (even lanes send pair-packed values -> 128 stores, tx 1024B/phase);
//   both CTAs finish tanh + h-update redundantly -> h stays CTA-local.
//   NL==2 fast path: fully unrolled, compile-time slot/parity/buffer indices.
// ---------------------------------------------------------------------------
#define LTC_H 256

__global__ __launch_bounds__(256, 1) __cluster_dims__(2, 1, 1)
void ltc_scan_kernel(
    const float* __restrict__ xproj,
    const float* __restrict__ Wrec,
    const float* __restrict__ brec,
    const float* __restrict__ tau,
    const int*   __restrict__ nl_p,
    float* __restrict__ out, int T)
{
    __shared__ __align__(16) float hbuf[2][LTC_H];
    __shared__ __align__(16) float ppart[2][LTC_H];
    __shared__ __align__(16) unsigned long long mbar[2];

    const int b = blockIdx.x >> 1;
    uint32_t rank;
    asm("mov.u32 %0, %%cluster_ctarank;" : "=r"(rank));
    const uint32_t peer = rank ^ 1u;

    const int t_ = threadIdx.x;              // output index 0..255

    // --- W_rec[t][rank*128 .. +127] -> 64 packed f32x2 registers ----------
    uint64_t wd[64];
    {
        const ulonglong2* wrow =
            (const ulonglong2*)(Wrec + (size_t)t_ * LTC_H + (rank << 7));
        #pragma unroll
        for (int i = 0; i < 32; i++) {
            ulonglong2 v = wrow[i];
            wd[2 * i]     = v.x;
            wd[2 * i + 1] = v.y;
        }
    }

    const float brec_j = brec[t_];
    const float scale_j = 0.1f / fminf(fmaxf(tau[t_], 0.1f), 5.0f);

    int NL = 2;
    if (nl_p) {
        int v = *nl_p;
        if (v >= 1 && v <= 64) NL = v;
    }

    const uint32_t mb[2] = { smem_u32(&mbar[0]), smem_u32(&mbar[1]) };
    if (t_ == 0) { mbar_init(mb[0], 1); mbar_init(mb[1], 1); }
    hbuf[0][t_] = 0.0f;
    hbuf[1][t_] = 0.0f;
    __syncthreads();
    CLUSTER_SYNC_();   // peer mbars + zeros visible before any st.async

    // remote (peer) targets; even lane sends the pair (t_, t_+1) as b64
    const uint32_t r_pp[2] = {
        mapa_rank(smem_u32(&ppart[0][t_ & ~1]), peer),
        mapa_rank(smem_u32(&ppart[1][t_ & ~1]), peer)
    };
    const uint32_t r_mb[2] = { mapa_rank(mb[0], peer), mapa_rank(mb[1], peer) };

    const float* xrow = xproj + ((size_t)b * T) * LTC_H + t_;
    float xt = __ldg(xrow);                  // prefetch t = 0
    float hj = 0.0f;
    const bool sender = !(t_ & 1);

    if (NL == 2) {
        for (int t = 0; t < T; t++) {
            const float base = xt + brec_j;
            if (t + 1 < T) xt = __ldg(xrow + (size_t)(t + 1) * LTC_H);
            const uint32_t par = (uint32_t)t & 1u;

            #pragma unroll
            for (int l = 0; l < 2; l++) {
                // arm this slot's phase (1 arrive + 1024B expected)
                if (t_ == 0) mbar_arrive_expect_tx(mb[l], LTC_H * 4u);

                // partial dot product over my K-half (h read = broadcast LDS)
                const ulonglong2* hp = (const ulonglong2*)(hbuf[l] + (rank << 7));
                uint64_t a0 = 0ull, a1 = 0ull, a2 = 0ull, a3 = 0ull;
                #pragma unroll
                for (int i = 0; i < 32; i += 2) {
                    ulonglong2 h0 = hp[i];
                    ulonglong2 h1 = hp[i + 1];
                    a0 = ffma2(wd[2 * i],     h0.x, a0);
                    a1 = ffma2(wd[2 * i + 1], h0.y, a1);
                    a2 = ffma2(wd[2 * i + 2], h1.x, a2);
                    a3 = ffma2(wd[2 * i + 3], h1.y, a3);
                }
                float part = (f2sum(a0) + f2sum(a1)) + (f2sum(a2) + f2sum(a3));

                // pair-pack + send (even lanes only): 128 x st.async.b64
                const float part_o = __shfl_xor_sync(0xffffffffu, part, 1);
                if (sender) st_async_b64(r_pp[l], pack2(part, part_o), r_mb[l]);

                // wait for the peer's partials for this slot
                mbar_wait_parity(mb[l], par);

                // finish output t_ redundantly (identical fp on both CTAs)
                const float sum = part + ppart[l][t_];
                const float act = my_tanh(base + sum);
                hj = fmaf(scale_j, act - hj, hj);

                hbuf[l ^ 1][t_] = hj;
                __syncthreads();
            }
        }
    } else {
        unsigned it = 0;
        uint32_t ph[2] = {0, 0};
        for (int t = 0; t < T; t++) {
            const float base = xt + brec_j;
            if (t + 1 < T) xt = __ldg(xrow + (size_t)(t + 1) * LTC_H);
            for (int l = 0; l < NL; l++) {
                const int slot = it & 1u;
                if (t_ == 0) mbar_arrive_expect_tx(mb[slot], LTC_H * 4u);

                const ulonglong2* hp = (const ulonglong2*)(hbuf[slot] + (rank << 7));
                uint64_t a0 = 0ull, a1 = 0ull, a2 = 0ull, a3 = 0ull;
                #pragma unroll
                for (int i = 0; i < 32; i += 2) {
                    ulonglong2 h0 = hp[i];
                    ulonglong2 h1 = hp[i + 1];
                    a0 = ffma2(wd[2 * i],     h0.x, a0);
                    a1 = ffma2(wd[2 * i + 1], h0.y, a1);
                    a2 = ffma2(wd[2 * i + 2], h1.x, a2);
                    a3 = ffma2(wd[2 * i + 3], h1.y, a3);
                }
                float part = (f2sum(a0) + f2sum(a1)) + (f2sum(a2) + f2sum(a3));
                const float part_o = __shfl_xor_sync(0xffffffffu, part, 1);
                if (sender) st_async_b64(r_pp[slot], pack2(part, part_o), r_mb[slot]);

                mbar_wait_parity(mb[slot], ph[slot]);
                ph[slot] ^= 1;

                const float sum = part + ppart[slot][t_];
                const float act = my_tanh(base + sum);
                hj = fmaf(scale_j, act - hj, hj);

                hbuf[slot ^ 1][t_] = hj;
                __syncthreads();
                it++;
            }
        }
    }

    if (rank == 0) out[(size_t)b * LTC_H + t_] = hj;

    CLUSTER_SYNC_();   // don't exit while peer st.async may target our smem
}

// ---------------------------------------------------------------------------
// Launcher — inputs: x, W_in, b_in, W_rec, b_rec, tau, num_layers
// ---------------------------------------------------------------------------
extern "C" void kernel_launch(void* const* d_in, const int* in_sizes, int n_in,
                              void* d_out, int out_size)
{
    const float* x    = (const float*)d_in[0];
    const float* Win  = (const float*)d_in[1];
    const float* bin  = (const float*)d_in[2];
    const float* Wrec = (const float*)d_in[3];
    const float* brec = (const float*)d_in[4];
    const float* tau  = (const float*)d_in[5];
    const int*   nl   = (n_in > 6) ? (const int*)d_in[6] : nullptr;

    const int H = in_sizes[2];              // 256
    const int I = in_sizes[1] / H;          // 128
    const int B = out_size / H;             // 64
    const int T = in_sizes[0] / (B * I);    // 4096
    const int M = B * T;

    float* xproj = nullptr;
    cudaGetSymbolAddress((void**)&xproj, g_xproj);

    dim3 grid1(H / XP_BN, M / XP_BM);
    xproj_kernel<<<grid1, 256>>>(x, Win, bin, xproj, M, I, H);

    ltc_scan_kernel<<<2 * B, LTC_H>>>(xproj, Wrec, brec, tau, nl,
                                      (float*)d_out, T);
}